// round 1
// baseline (speedup 1.0000x reference)
#include <cuda_runtime.h>

#define T_LEN   4096
#define IN_SZ   128
#define R_SZ    2048
#define NCTA    128
#define ROWS_PER_CTA 16     // 2048 / 128
#define THREADS_SCAN 256
#define INV_SQRT_R 0.022097086912079608f   // 1/sqrt(2048)

// Scratch: batched input projection U[t][r] = input[t] @ W_in^T + bias
__device__ float g_U[(size_t)T_LEN * R_SZ];
__device__ unsigned int g_bar;

// ---------------------------------------------------------------------------
// Reset the grid barrier counter (must run before scan_kernel each launch).
// ---------------------------------------------------------------------------
__global__ void init_kernel() { g_bar = 0u; }

// ---------------------------------------------------------------------------
// Projection GEMM: U = input @ W_in^T + bias.  (4096 x 2048, K=128)
// 64x64 tile per block, 4x4 microtile per thread, k-major SMEM staging.
// ---------------------------------------------------------------------------
#define PJ_KT 32
__global__ __launch_bounds__(256) void proj_kernel(
    const float* __restrict__ inp,   // [T_LEN][IN_SZ]
    const float* __restrict__ Win,   // [R_SZ][IN_SZ]
    const float* __restrict__ bias)  // [R_SZ]
{
    __shared__ float sA[PJ_KT][64];  // [k][t]
    __shared__ float sB[PJ_KT][64];  // [k][r]

    const int tid = threadIdx.x;
    const int t0 = blockIdx.y * 64;
    const int r0 = blockIdx.x * 64;
    const int tx = tid & 15;   // t sub-index
    const int ty = tid >> 4;   // r sub-index

    float acc[4][4];
#pragma unroll
    for (int i = 0; i < 4; i++)
#pragma unroll
        for (int j = 0; j < 4; j++) acc[i][j] = 0.0f;

    for (int kc = 0; kc < IN_SZ; kc += PJ_KT) {
        __syncthreads();   // protect previous chunk's SMEM from overwrite
        // Stage 64 rows x 32 k (2048 floats each): 512 float4, 2 per thread
#pragma unroll
        for (int it = 0; it < 2; it++) {
            int i   = tid + 256 * it;   // 0..511
            int row = i >> 3;           // 0..63
            int kq  = i & 7;            // float4 index in chunk
            float4 va = *(const float4*)(inp + (size_t)(t0 + row) * IN_SZ + kc + 4 * kq);
            sA[4 * kq + 0][row] = va.x;
            sA[4 * kq + 1][row] = va.y;
            sA[4 * kq + 2][row] = va.z;
            sA[4 * kq + 3][row] = va.w;
            float4 vb = *(const float4*)(Win + (size_t)(r0 + row) * IN_SZ + kc + 4 * kq);
            sB[4 * kq + 0][row] = vb.x;
            sB[4 * kq + 1][row] = vb.y;
            sB[4 * kq + 2][row] = vb.z;
            sB[4 * kq + 3][row] = vb.w;
        }
        __syncthreads();
#pragma unroll
        for (int k = 0; k < PJ_KT; k++) {
            float a[4], b[4];
#pragma unroll
            for (int i = 0; i < 4; i++) a[i] = sA[k][tx + 16 * i];
#pragma unroll
            for (int j = 0; j < 4; j++) b[j] = sB[k][ty + 16 * j];
#pragma unroll
            for (int i = 0; i < 4; i++)
#pragma unroll
                for (int j = 0; j < 4; j++) acc[i][j] += a[i] * b[j];
        }
    }

#pragma unroll
    for (int j = 0; j < 4; j++) {
        const int r = r0 + ty + 16 * j;
        const float bj = bias[r];
#pragma unroll
        for (int i = 0; i < 4; i++) {
            const int t = t0 + tx + 16 * i;
            g_U[(size_t)t * R_SZ + r] = acc[i][j] + bj;
        }
    }
}

// ---------------------------------------------------------------------------
// Persistent ESN scan. 128 CTAs (all co-resident), 16 rows each.
// W_res rows live permanently in registers (128 floats/thread).
// Each step: grid barrier -> load s=out[t-1] to SMEM -> matvec -> shfl reduce
// -> erf/leak update -> write out[t].
// ---------------------------------------------------------------------------
__global__ __launch_bounds__(THREADS_SCAN, 1) void scan_kernel(
    const float* __restrict__ Wres,  // [R_SZ][R_SZ]
    float* __restrict__ out)         // [T_LEN][R_SZ]
{
    __shared__ float4 s_sm4[R_SZ / 4];   // full state, 8 KB
    const float* s_sm = (const float*)s_sm4;

    const int tid  = threadIdx.x;
    const int warp = tid >> 5;
    const int lane = tid & 31;
    const int rowA = blockIdx.x * ROWS_PER_CTA + 2 * warp;
    const int rowB = rowA + 1;

    // Preload weights into registers.
    // Thread (warp w, lane l) owns rows {rowA,rowB}, columns 4*l + 128*k (+0..3), k=0..15.
    float4 wA[16], wB[16];
    {
        const float* pA = Wres + (size_t)rowA * R_SZ + 4 * lane;
        const float* pB = Wres + (size_t)rowB * R_SZ + 4 * lane;
#pragma unroll
        for (int k = 0; k < 16; k++) {
            wA[k] = *(const float4*)(pA + 128 * k);
            wB[k] = *(const float4*)(pB + 128 * k);
        }
    }

    for (int t = 0; t < T_LEN; t++) {
        // ---- bring state into SMEM ----
        if (t == 0) {
            for (int i = tid; i < R_SZ / 4; i += THREADS_SCAN)
                s_sm4[i] = make_float4(0.f, 0.f, 0.f, 0.f);
        } else {
            const float4* prev = (const float4*)(out + (size_t)(t - 1) * R_SZ);
            for (int i = tid; i < R_SZ / 4; i += THREADS_SCAN)
                s_sm4[i] = __ldcg(prev + i);   // L2-only: always fresh
        }
        __syncthreads();

        // ---- register-resident matvec ----
        float a0 = 0.f, a1 = 0.f;
#pragma unroll
        for (int k = 0; k < 16; k++) {
            const float4 s4 = s_sm4[lane + 32 * k];
            a0 += wA[k].x * s4.x; a0 += wA[k].y * s4.y;
            a0 += wA[k].z * s4.z; a0 += wA[k].w * s4.w;
            a1 += wB[k].x * s4.x; a1 += wB[k].y * s4.y;
            a1 += wB[k].z * s4.z; a1 += wB[k].w * s4.w;
        }

        // ---- warp reduction (2 rows per warp) ----
#pragma unroll
        for (int off = 16; off > 0; off >>= 1) {
            a0 += __shfl_xor_sync(0xffffffffu, a0, off);
            a1 += __shfl_xor_sync(0xffffffffu, a1, off);
        }

        if (lane == 0) {
            const float u0 = g_U[(size_t)t * R_SZ + rowA];
            const float u1 = g_U[(size_t)t * R_SZ + rowB];
            const float so0 = s_sm[rowA];
            const float so1 = s_sm[rowB];
            const float x0 = 0.1f * so0 + 0.9f * erff(a0 + u0) * INV_SQRT_R;
            const float x1 = 0.1f * so1 + 0.9f * erff(a1 + u1) * INV_SQRT_R;
            out[(size_t)t * R_SZ + rowA] = x0;
            out[(size_t)t * R_SZ + rowB] = x1;
            __threadfence();   // writer's stores -> GPU scope before arrival
        }

        // ---- grid-wide barrier ----
        if (t < T_LEN - 1) {
            __syncthreads();                  // all warps' writes fenced
            if (tid == 0) {
                atomicAdd(&g_bar, 1u);
                const unsigned tgt = (unsigned)(t + 1) * NCTA;
                while (*(volatile unsigned int*)&g_bar < tgt) { }
            }
            __syncthreads();
        }
    }
}

// ---------------------------------------------------------------------------
extern "C" void kernel_launch(void* const* d_in, const int* in_sizes, int n_in,
                              void* d_out, int out_size)
{
    const float* input = (const float*)d_in[0];  // [4096][128]
    const float* Win   = (const float*)d_in[1];  // [2048][128]
    const float* Wres  = (const float*)d_in[2];  // [2048][2048]
    const float* bias  = (const float*)d_in[3];  // [2048]
    float* out = (float*)d_out;                  // [4096][2048]

    init_kernel<<<1, 1>>>();

    dim3 pg(R_SZ / 64, T_LEN / 64);              // (32, 64)
    proj_kernel<<<pg, 256>>>(input, Win, bias);

    scan_kernel<<<NCTA, THREADS_SCAN>>>(Wres, out);
}